// round 4
// baseline (speedup 1.0000x reference)
#include <cuda_runtime.h>
#include <math.h>

#define BB 128
#define TT 512
#define ENC 512
#define HHD 512
#define AA 18
#define MM (BB*TT)
#define G4 (4*HHD)

#define N_LOGITS ((size_t)MM*AA)
#define OFF_LOGITS ((size_t)0)
#define OFF_VALUES (N_LOGITS)
#define OFF_HT (OFF_VALUES + (size_t)MM)
#define OFF_CT (OFF_HT + (size_t)BB*HHD)
#define OFF_AR (OFF_CT + (size_t)BB*HHD)
#define OFF_TAR (OFF_AR + 1)
#define NGATE ((size_t)MM*HHD)
#define OFF_IG (OFF_TAR + 1)
#define OFF_FG (OFF_IG + NGATE)
#define OFF_GG (OFF_FG + NGATE)
#define OFF_OG (OFF_GG + NGATE)

__device__ __align__(16) float g_enc1[(size_t)MM*ENC];   // enc1; later reused as LSTM out (B,T,H)
__device__ __align__(16) float g_enc2[(size_t)MM*ENC];
__device__ __align__(16) float g_xg[(size_t)MM*G4];
__device__ __align__(16) float g_h[2][BB*HHD];
#define LOSS_BLOCKS 2048
__device__ double g_part[2][LOSS_BLOCKS];
__device__ unsigned g_arrive;
__device__ unsigned g_release;

__device__ __forceinline__ float sigf(float x){ return 1.f/(1.f+expf(-x)); }
__device__ __forceinline__ void fma2(unsigned long long& d, unsigned long long a, unsigned long long b){
    asm("fma.rn.f32x2 %0, %1, %2, %0;" : "+l"(d) : "l"(a), "l"(b));
}
__device__ __forceinline__ void unpack2(unsigned long long v, float& lo, float& hi){
    unsigned l,h; asm("mov.b64 {%0, %1}, %2;" : "=r"(l), "=r"(h) : "l"(v));
    lo=__uint_as_float(l); hi=__uint_as_float(h);
}

// ================= GEMM (NT) =================
// C[m][n] = act(sum_k A[m][k]*B[n][k] + bias1[n] (+bias2[n]))
// BM=BN=128, BK=16, 256 threads, 8x8 thread tile.
// A stored DUPLICATED in smem ({a,a} pairs) so FFMA2 needs no per-kk MOV dup;
// B read as natural adjacent-column pairs. acc pairs run along N.
template<int ACT>
__global__ __launch_bounds__(256)
void gemm_nt(const float* __restrict__ A, const float* __restrict__ Bm,
             const float* __restrict__ bias1, const float* __restrict__ bias2,
             float* __restrict__ C, int K, int N)
{
    __shared__ __align__(16) float As2[16*266];
    __shared__ __align__(16) float Bs[16*132];
    const int tid = threadIdx.x;
    const int tx = tid & 15, ty = tid >> 4;
    const float* Ab = A + (size_t)blockIdx.y * 128 * K;
    const float* Bb = Bm + (size_t)blockIdx.x * 128 * K;

    const int l0 = tid, l1 = tid + 256;
    const int row0 = l0 >> 2, c40 = (l0 & 3) << 2;
    const int row1 = l1 >> 2, c41 = (l1 & 3) << 2;

    unsigned long long acc[8][4];
#pragma unroll
    for (int i=0;i<8;i++)
#pragma unroll
        for (int j=0;j<4;j++) acc[i][j]=0ull;

    const int nk = K >> 4;
    float4 pa0, pa1, pb0, pb1;
    // preload tile 0
    pa0 = __ldcg((const float4*)(Ab + (size_t)row0*K + c40));
    pb0 = __ldcg((const float4*)(Bb + (size_t)row0*K + c40));
    pa1 = __ldcg((const float4*)(Ab + (size_t)row1*K + c41));
    pb1 = __ldcg((const float4*)(Bb + (size_t)row1*K + c41));
    {
        *(float2*)&As2[(c40+0)*266 + 2*row0] = make_float2(pa0.x, pa0.x);
        *(float2*)&As2[(c40+1)*266 + 2*row0] = make_float2(pa0.y, pa0.y);
        *(float2*)&As2[(c40+2)*266 + 2*row0] = make_float2(pa0.z, pa0.z);
        *(float2*)&As2[(c40+3)*266 + 2*row0] = make_float2(pa0.w, pa0.w);
        Bs[(c40+0)*132 + row0] = pb0.x; Bs[(c40+1)*132 + row0] = pb0.y;
        Bs[(c40+2)*132 + row0] = pb0.z; Bs[(c40+3)*132 + row0] = pb0.w;
        *(float2*)&As2[(c41+0)*266 + 2*row1] = make_float2(pa1.x, pa1.x);
        *(float2*)&As2[(c41+1)*266 + 2*row1] = make_float2(pa1.y, pa1.y);
        *(float2*)&As2[(c41+2)*266 + 2*row1] = make_float2(pa1.z, pa1.z);
        *(float2*)&As2[(c41+3)*266 + 2*row1] = make_float2(pa1.w, pa1.w);
        Bs[(c41+0)*132 + row1] = pb1.x; Bs[(c41+1)*132 + row1] = pb1.y;
        Bs[(c41+2)*132 + row1] = pb1.z; Bs[(c41+3)*132 + row1] = pb1.w;
    }
    __syncthreads();

    for (int kt=0; kt<nk; kt++){
        if (kt+1 < nk){
            int k0 = (kt+1) << 4;
            pa0 = __ldcg((const float4*)(Ab + (size_t)row0*K + k0 + c40));
            pb0 = __ldcg((const float4*)(Bb + (size_t)row0*K + k0 + c40));
            pa1 = __ldcg((const float4*)(Ab + (size_t)row1*K + k0 + c41));
            pb1 = __ldcg((const float4*)(Bb + (size_t)row1*K + k0 + c41));
        }
#pragma unroll
        for (int kk=0;kk<16;kk++){
            const float* as = &As2[kk*266 + ty*16];
            unsigned long long da[8];
#pragma unroll
            for (int i=0;i<8;i++) da[i] = *(const unsigned long long*)(as + 2*i);
            const float* bs = &Bs[kk*132 + tx*8];
            ulonglong2 u0 = *(const ulonglong2*)bs;
            ulonglong2 u1 = *(const ulonglong2*)(bs+4);
            unsigned long long bp[4] = { u0.x, u0.y, u1.x, u1.y };
#pragma unroll
            for (int i=0;i<8;i++)
#pragma unroll
                for (int j=0;j<4;j++) fma2(acc[i][j], da[i], bp[j]);
        }
        __syncthreads();
        if (kt+1 < nk){
            *(float2*)&As2[(c40+0)*266 + 2*row0] = make_float2(pa0.x, pa0.x);
            *(float2*)&As2[(c40+1)*266 + 2*row0] = make_float2(pa0.y, pa0.y);
            *(float2*)&As2[(c40+2)*266 + 2*row0] = make_float2(pa0.z, pa0.z);
            *(float2*)&As2[(c40+3)*266 + 2*row0] = make_float2(pa0.w, pa0.w);
            Bs[(c40+0)*132 + row0] = pb0.x; Bs[(c40+1)*132 + row0] = pb0.y;
            Bs[(c40+2)*132 + row0] = pb0.z; Bs[(c40+3)*132 + row0] = pb0.w;
            *(float2*)&As2[(c41+0)*266 + 2*row1] = make_float2(pa1.x, pa1.x);
            *(float2*)&As2[(c41+1)*266 + 2*row1] = make_float2(pa1.y, pa1.y);
            *(float2*)&As2[(c41+2)*266 + 2*row1] = make_float2(pa1.z, pa1.z);
            *(float2*)&As2[(c41+3)*266 + 2*row1] = make_float2(pa1.w, pa1.w);
            Bs[(c41+0)*132 + row1] = pb1.x; Bs[(c41+1)*132 + row1] = pb1.y;
            Bs[(c41+2)*132 + row1] = pb1.z; Bs[(c41+3)*132 + row1] = pb1.w;
            __syncthreads();
        }
    }

    const int colb = blockIdx.x*128 + tx*8;
    float bv[8];
#pragma unroll
    for (int j=0;j<8;j++) bv[j] = bias1[colb+j] + (bias2 ? bias2[colb+j] : 0.f);
    const size_t rowb = (size_t)blockIdx.y*128 + ty*8;
#pragma unroll
    for (int i=0;i<8;i++){
        float v[8];
#pragma unroll
        for (int j=0;j<4;j++){
            float x0,x1; unpack2(acc[i][j],x0,x1);
            x0 += bv[2*j]; x1 += bv[2*j+1];
            if (ACT==1){ x0 = x0/(1.f+expf(-x0)); x1 = x1/(1.f+expf(-x1)); }
            v[2*j]=x0; v[2*j+1]=x1;
        }
        float* c0 = C + (rowb + i)*(size_t)N + colb;
        *(float4*)(c0)   = make_float4(v[0],v[1],v[2],v[3]);
        *(float4*)(c0+4) = make_float4(v[4],v[5],v[6],v[7]);
    }
}

__global__ void init_kernel(const float* __restrict__ hxs)
{
    if (blockIdx.x==0 && threadIdx.x==0){ g_arrive=0u; g_release=0u; }
    size_t i = (size_t)blockIdx.x*256 + threadIdx.x;
    ((float4*)g_h[0])[i] = ((const float4*)hxs)[i];
}

// ================= Persistent LSTM =================
// 128 blocks = 4 b-tiles(32 rows) x 32 h-tiles(16 h), 256 threads.
// Per-SM weight set = 16h x 4g x 2KB = 128KB -> L1-resident (no fences/IVALL).
// h crosses SMs: __ldcv. xg streamed: __ldcg. Barrier: release-atomic arrive +
// acquire poll (no L1 flush).
__global__ __launch_bounds__(256)
void lstm_kernel(const float* __restrict__ Whh, const float* __restrict__ cxs,
                 float* __restrict__ dout)
{
    __shared__ __align__(16) float STb[5*32*16];
#define ST(a,r,q) STb[(((a)*32+(r))*16)+(q)]
    const int tid = threadIdx.x;
    const int b0 = (blockIdx.x & 3) * 32;
    const int hbase = (blockIdx.x >> 2) * 16;
    const int hloc = tid >> 4;        // 0..15
    const int bg = tid & 15;          // 0..15 -> 2 b rows
    const int h = hbase + hloc;
    const int rA = bg*2, rB = rA+1;
    const int bA = b0+rA, bB = b0+rB;

    const float* w0 = Whh + (size_t)(0*HHD + h)*HHD;
    const float* w1 = Whh + (size_t)(1*HHD + h)*HHD;
    const float* w2 = Whh + (size_t)(2*HHD + h)*HHD;
    const float* w3 = Whh + (size_t)(3*HHD + h)*HHD;

    float cA = cxs[(size_t)bA*HHD + h];
    float cB = cxs[(size_t)bB*HHD + h];

    float* outb = g_enc1;
    float* gp1 = dout + OFF_IG;  float* gp2 = dout + OFF_FG;
    float* gp3 = dout + OFF_GG;  float* gp4 = dout + OFF_OG;

    for (int t=0;t<TT;t++){
        const float* hin = g_h[t&1];
        float* hnx = g_h[(t+1)&1];
        const float* hArow = hin + (size_t)bA*HHD;
        const float* hBrow = hin + (size_t)bB*HHD;

        float a0=0.f,a1=0.f,a2=0.f,a3=0.f,d0=0.f,d1=0.f,d2=0.f,d3=0.f;
#pragma unroll 4
        for (int k=0;k<HHD;k+=4){
            float4 wa = __ldg((const float4*)(w0+k));
            float4 wb = __ldg((const float4*)(w1+k));
            float4 wc = __ldg((const float4*)(w2+k));
            float4 wd = __ldg((const float4*)(w3+k));
            float4 hA = __ldcv((const float4*)(hArow+k));
            float4 hB = __ldcv((const float4*)(hBrow+k));
            a0 += hA.x*wa.x + hA.y*wa.y + hA.z*wa.z + hA.w*wa.w;
            a1 += hA.x*wb.x + hA.y*wb.y + hA.z*wb.z + hA.w*wb.w;
            a2 += hA.x*wc.x + hA.y*wc.y + hA.z*wc.z + hA.w*wc.w;
            a3 += hA.x*wd.x + hA.y*wd.y + hA.z*wd.z + hA.w*wd.w;
            d0 += hB.x*wa.x + hB.y*wa.y + hB.z*wa.z + hB.w*wa.w;
            d1 += hB.x*wb.x + hB.y*wb.y + hB.z*wb.z + hB.w*wb.w;
            d2 += hB.x*wc.x + hB.y*wc.y + hB.z*wc.z + hB.w*wc.w;
            d3 += hB.x*wd.x + hB.y*wd.y + hB.z*wd.z + hB.w*wd.w;
        }

        const size_t xbA = ((size_t)bA*TT + t)*G4 + h;
        const size_t xbB = ((size_t)bB*TT + t)*G4 + h;
        float iA = sigf(a0 + __ldcg(g_xg + xbA + 0*HHD));
        float fA = sigf(a1 + __ldcg(g_xg + xbA + 1*HHD));
        float gA = tanhf(a2 + __ldcg(g_xg + xbA + 2*HHD));
        float oA = sigf(a3 + __ldcg(g_xg + xbA + 3*HHD));
        float iB = sigf(d0 + __ldcg(g_xg + xbB + 0*HHD));
        float fB = sigf(d1 + __ldcg(g_xg + xbB + 1*HHD));
        float gB = tanhf(d2 + __ldcg(g_xg + xbB + 2*HHD));
        float oB = sigf(d3 + __ldcg(g_xg + xbB + 3*HHD));
        cA = fA*cA + iA*gA;  cB = fB*cB + iB*gB;
        float hAo = oA*tanhf(cA), hBo = oB*tanhf(cB);

        ST(0,rA,hloc)=hAo; ST(0,rB,hloc)=hBo;
        ST(1,rA,hloc)=iA;  ST(1,rB,hloc)=iB;
        ST(2,rA,hloc)=fA;  ST(2,rB,hloc)=fB;
        ST(3,rA,hloc)=gA;  ST(3,rB,hloc)=gB;
        ST(4,rA,hloc)=oA;  ST(4,rB,hloc)=oB;
        __syncthreads();

        // h: 128 float4 slots; gates: 1024 float2 slots (gate sections of d_out
        // are only 8B-aligned: OFF_IG*4 == 8 mod 16).
        for (int l=tid;l<1152;l+=256){
            if (l < 128){
                int r = l>>2, q4 = (l&3)<<2;
                float4 v = *(const float4*)&ST(0,r,q4);
                *(float4*)(hnx + (size_t)(b0+r)*HHD + hbase + q4) = v;
                *(float4*)(outb + ((size_t)(b0+r)*TT + t)*HHD + hbase + q4) = v;
            } else {
                int m = l - 128;
                int a = m >> 8;
                int r = (m >> 3) & 31;
                int q2 = (m & 7) << 1;
                float2 v = *(const float2*)&ST(a+1,r,q2);
                size_t base = ((size_t)(b0+r)*TT + t)*HHD + hbase + q2;
                float* gp = (a==0) ? gp1 : (a==1) ? gp2 : (a==2) ? gp3 : gp4;
                *(float2*)(gp + base) = v;
            }
        }

        if (t==TT-1){
            dout[OFF_HT + (size_t)bA*HHD + h] = hAo;
            dout[OFF_HT + (size_t)bB*HHD + h] = hBo;
            dout[OFF_CT + (size_t)bA*HHD + h] = cA;
            dout[OFF_CT + (size_t)bB*HHD + h] = cB;
        }

        __syncthreads();   // all stores (incl. hnx) done before arrive
        if (tid==0){
            unsigned v;
            asm volatile("atom.release.gpu.global.add.u32 %0, [%1], %2;"
                         : "=r"(v) : "l"(&g_arrive), "r"(1u) : "memory");
            if (v == 127u){
                g_arrive = 0u;   // all arrived; reset happens-before release store
                asm volatile("st.release.gpu.global.u32 [%0], %1;"
                             :: "l"(&g_release), "r"((unsigned)(t+1)) : "memory");
            } else {
                unsigned r;
                do {
                    asm volatile("ld.acquire.gpu.global.u32 %0, [%1];"
                                 : "=r"(r) : "l"(&g_release) : "memory");
                } while (r < (unsigned)(t+1));
            }
        }
        __syncthreads();
    }
#undef ST
}

__global__ __launch_bounds__(256)
void head_kernel(const float* __restrict__ Wa, const float* __restrict__ ba,
                 const float* __restrict__ Wc, const float* __restrict__ bc,
                 float* __restrict__ dout)
{
    __shared__ __align__(16) float xsr[16][516];
    const int tid = threadIdx.x;
    const size_t m0 = (size_t)blockIdx.x * 16;
    for (int l=tid;l<2048;l+=256){
        int r=l>>7, c4=(l&127)<<2;
        *(float4*)&xsr[r][c4] = *(const float4*)(g_enc1 + (m0+r)*HHD + c4);
    }
    __syncthreads();
    for (int o=tid;o<16*19;o+=256){
        int r=o/19, n=o-r*19;
        const float* wrow = (n<18) ? (Wa + (size_t)n*HHD) : Wc;
        float acc=0.f;
#pragma unroll 4
        for (int k=0;k<HHD;k+=4){
            float4 w = __ldg((const float4*)(wrow+k));
            float4 x = *(const float4*)&xsr[r][k];
            acc += x.x*w.x + x.y*w.y + x.z*w.z + x.w*w.w;
        }
        size_t m = m0 + r;
        if (n<18) dout[OFF_LOGITS + m*AA + n] = acc + ba[n];
        else      dout[OFF_VALUES + m] = acc + bc[0];
    }
}

__global__ __launch_bounds__(256)
void loss_partial()
{
    float s1=0.f, s2=0.f;
    const size_t n = (size_t)MM*HHD;
    for (size_t i=(size_t)blockIdx.x*256+threadIdx.x; i<n; i+=(size_t)LOSS_BLOCKS*256){
        float x = g_enc1[i];
        s1 += x*x;
        unsigned t = ((unsigned)(i>>9)) & 511u;
        if (t != 511u){ float d = g_enc1[i+512] - x; s2 += d*d; }
    }
    __shared__ double r1[256], r2[256];
    r1[threadIdx.x]=(double)s1; r2[threadIdx.x]=(double)s2;
    __syncthreads();
    for (int s=128;s>0;s>>=1){
        if (threadIdx.x<s){ r1[threadIdx.x]+=r1[threadIdx.x+s]; r2[threadIdx.x]+=r2[threadIdx.x+s]; }
        __syncthreads();
    }
    if (threadIdx.x==0){ g_part[0][blockIdx.x]=r1[0]; g_part[1][blockIdx.x]=r2[0]; }
}

__global__ void loss_final(float* __restrict__ dout)
{
    __shared__ double r1[256], r2[256];
    double s1=0.0, s2=0.0;
    for (int i=threadIdx.x;i<LOSS_BLOCKS;i+=256){ s1+=g_part[0][i]; s2+=g_part[1][i]; }
    r1[threadIdx.x]=s1; r2[threadIdx.x]=s2;
    __syncthreads();
    for (int s=128;s>0;s>>=1){
        if (threadIdx.x<s){ r1[threadIdx.x]+=r1[threadIdx.x+s]; r2[threadIdx.x]+=r2[threadIdx.x+s]; }
        __syncthreads();
    }
    if (threadIdx.x==0){
        dout[OFF_AR]  = (float)(r1[0] * (0.01 / ((double)MM * HHD)));
        dout[OFF_TAR] = (float)(r2[0] * (0.01 / ((double)BB * (TT-1) * HHD)));
    }
}

extern "C" void kernel_launch(void* const* d_in, const int* in_sizes, int n_in,
                              void* d_out, int out_size)
{
    const float* obs  = (const float*)d_in[0];
    const float* hxs  = (const float*)d_in[1];
    const float* cxs  = (const float*)d_in[2];
    const float* W1   = (const float*)d_in[3];
    const float* b1   = (const float*)d_in[4];
    const float* W2   = (const float*)d_in[5];
    const float* b2   = (const float*)d_in[6];
    const float* W_ih = (const float*)d_in[7];
    const float* W_hh = (const float*)d_in[8];
    const float* b_ih = (const float*)d_in[9];
    const float* b_hh = (const float*)d_in[10];
    const float* Wa   = (const float*)d_in[11];
    const float* ba   = (const float*)d_in[12];
    const float* Wc   = (const float*)d_in[13];
    const float* bc   = (const float*)d_in[14];
    float* dout = (float*)d_out;

    float* enc1; cudaGetSymbolAddress((void**)&enc1, g_enc1);
    float* enc2; cudaGetSymbolAddress((void**)&enc2, g_enc2);
    float* xg;   cudaGetSymbolAddress((void**)&xg,   g_xg);

    init_kernel<<<64, 256>>>(hxs);   // first, so ncu skip-5 lands on gemm3
    // enc1 = silu(obs @ W1^T + b1)   [65536 x 512, K=128]
    gemm_nt<1><<<dim3(ENC/128, MM/128), 256>>>(obs, W1, b1, nullptr, enc1, 128, ENC);
    // enc2 = silu(enc1 @ W2^T + b2)  [65536 x 512, K=512]
    gemm_nt<1><<<dim3(ENC/128, MM/128), 256>>>(enc1, W2, b2, nullptr, enc2, ENC, ENC);
    // xg = enc2 @ W_ih^T + b_ih + b_hh   [65536 x 2048, K=512]
    gemm_nt<0><<<dim3(G4/128, MM/128), 256>>>(enc2, W_ih, b_ih, b_hh, xg, ENC, G4);

    lstm_kernel<<<128, 256>>>(W_hh, cxs, dout);
    head_kernel<<<MM/16, 256>>>(Wa, ba, Wc, bc, dout);
    loss_partial<<<LOSS_BLOCKS, 256>>>();
    loss_final<<<1, 256>>>(dout);
}

// round 5
// speedup vs baseline: 1.9688x; 1.9688x over previous
#include <cuda_runtime.h>
#include <math.h>

#define BB 128
#define TT 512
#define ENC 512
#define HHD 512
#define AA 18
#define MM (BB*TT)
#define G4 (4*HHD)

#define N_LOGITS ((size_t)MM*AA)
#define OFF_LOGITS ((size_t)0)
#define OFF_VALUES (N_LOGITS)
#define OFF_HT (OFF_VALUES + (size_t)MM)
#define OFF_CT (OFF_HT + (size_t)BB*HHD)
#define OFF_AR (OFF_CT + (size_t)BB*HHD)
#define OFF_TAR (OFF_AR + 1)
#define NGATE ((size_t)MM*HHD)
#define OFF_IG (OFF_TAR + 1)
#define OFF_FG (OFF_IG + NGATE)
#define OFF_GG (OFF_FG + NGATE)
#define OFF_OG (OFF_GG + NGATE)

__device__ __align__(16) float g_enc1[(size_t)MM*ENC];   // enc1; later reused as LSTM out (B,T,H)
__device__ __align__(16) float g_enc2[(size_t)MM*ENC];
__device__ __align__(16) float g_xg[(size_t)MM*G4];
__device__ __align__(16) float g_h[2][BB*HHD];
#define LOSS_BLOCKS 2048
__device__ double g_part[2][LOSS_BLOCKS];
__device__ unsigned g_arrive;
__device__ unsigned g_release;

__device__ __forceinline__ float sigf(float x){ return 1.f/(1.f+expf(-x)); }
__device__ __forceinline__ unsigned long long f2dup(float x){
    unsigned long long r; asm("mov.b64 %0, {%1, %1};" : "=l"(r) : "r"(__float_as_uint(x))); return r;
}
__device__ __forceinline__ void fma2(unsigned long long& d, unsigned long long a, unsigned long long b){
    asm("fma.rn.f32x2 %0, %1, %2, %0;" : "+l"(d) : "l"(a), "l"(b));
}
__device__ __forceinline__ void unpack2(unsigned long long v, float& lo, float& hi){
    unsigned l,h; asm("mov.b64 {%0, %1}, %2;" : "=r"(l), "=r"(h) : "l"(v));
    lo=__uint_as_float(l); hi=__uint_as_float(h);
}

// ================= GEMM (NT) =================
// C[m][n] = act(sum_k A[m][k]*B[n][k] + bias1[n] (+bias2[n]))
// BM=BN=128, BK=16, 256 threads, 8x8 thread tile.
// Natural smem layouts (A pairs along M via LDS.128; B dup'd in regs via MOV).
// Double-buffered smem, ONE __syncthreads per k-tile, LDG prefetch.
template<int ACT>
__global__ __launch_bounds__(256)
void gemm_nt(const float* __restrict__ A, const float* __restrict__ Bm,
             const float* __restrict__ bias1, const float* __restrict__ bias2,
             float* __restrict__ C, int K, int N)
{
    __shared__ __align__(16) float As[2][16][132];
    __shared__ __align__(16) float Bs[2][16][132];
    const int tid = threadIdx.x;
    const int tx = tid & 15, ty = tid >> 4;
    const float* Ab = A + (size_t)blockIdx.y * 128 * K;
    const float* Bb = Bm + (size_t)blockIdx.x * 128 * K;

    const int row0 = tid >> 2, c4 = (tid & 3) << 2;
    const int row1 = row0 + 64;

    unsigned long long acc[4][8];
#pragma unroll
    for (int i=0;i<4;i++)
#pragma unroll
        for (int j=0;j<8;j++) acc[i][j]=0ull;

    const int nk = K >> 4;
    // load tile 0 into buf 0
    {
        float4 a0 = __ldcg((const float4*)(Ab + (size_t)row0*K + c4));
        float4 b0 = __ldcg((const float4*)(Bb + (size_t)row0*K + c4));
        float4 a1 = __ldcg((const float4*)(Ab + (size_t)row1*K + c4));
        float4 b1 = __ldcg((const float4*)(Bb + (size_t)row1*K + c4));
        As[0][c4+0][row0]=a0.x; As[0][c4+1][row0]=a0.y; As[0][c4+2][row0]=a0.z; As[0][c4+3][row0]=a0.w;
        Bs[0][c4+0][row0]=b0.x; Bs[0][c4+1][row0]=b0.y; Bs[0][c4+2][row0]=b0.z; Bs[0][c4+3][row0]=b0.w;
        As[0][c4+0][row1]=a1.x; As[0][c4+1][row1]=a1.y; As[0][c4+2][row1]=a1.z; As[0][c4+3][row1]=a1.w;
        Bs[0][c4+0][row1]=b1.x; Bs[0][c4+1][row1]=b1.y; Bs[0][c4+2][row1]=b1.z; Bs[0][c4+3][row1]=b1.w;
    }
    __syncthreads();

    int buf = 0;
    for (int kt=0; kt<nk; kt++){
        float4 pa0, pb0, pa1, pb1;
        const bool more = (kt+1 < nk);
        if (more){
            int k0 = (kt+1) << 4;
            pa0 = __ldcg((const float4*)(Ab + (size_t)row0*K + k0 + c4));
            pb0 = __ldcg((const float4*)(Bb + (size_t)row0*K + k0 + c4));
            pa1 = __ldcg((const float4*)(Ab + (size_t)row1*K + k0 + c4));
            pb1 = __ldcg((const float4*)(Bb + (size_t)row1*K + k0 + c4));
        }
#pragma unroll
        for (int kk=0;kk<16;kk++){
            ulonglong2 ua = *(const ulonglong2*)&As[buf][kk][ty*8];
            ulonglong2 ub = *(const ulonglong2*)&As[buf][kk][ty*8+4];
            unsigned long long ap[4] = { ua.x, ua.y, ub.x, ub.y };
            float4 f0 = *(const float4*)&Bs[buf][kk][tx*8];
            float4 f1 = *(const float4*)&Bs[buf][kk][tx*8+4];
            unsigned long long bd[8] = { f2dup(f0.x),f2dup(f0.y),f2dup(f0.z),f2dup(f0.w),
                                         f2dup(f1.x),f2dup(f1.y),f2dup(f1.z),f2dup(f1.w) };
#pragma unroll
            for (int i=0;i<4;i++)
#pragma unroll
                for (int j=0;j<8;j++) fma2(acc[i][j], ap[i], bd[j]);
        }
        if (more){
            int nb = buf ^ 1;
            As[nb][c4+0][row0]=pa0.x; As[nb][c4+1][row0]=pa0.y; As[nb][c4+2][row0]=pa0.z; As[nb][c4+3][row0]=pa0.w;
            Bs[nb][c4+0][row0]=pb0.x; Bs[nb][c4+1][row0]=pb0.y; Bs[nb][c4+2][row0]=pb0.z; Bs[nb][c4+3][row0]=pb0.w;
            As[nb][c4+0][row1]=pa1.x; As[nb][c4+1][row1]=pa1.y; As[nb][c4+2][row1]=pa1.z; As[nb][c4+3][row1]=pa1.w;
            Bs[nb][c4+0][row1]=pb1.x; Bs[nb][c4+1][row1]=pb1.y; Bs[nb][c4+2][row1]=pb1.z; Bs[nb][c4+3][row1]=pb1.w;
            __syncthreads();
            buf = nb;
        }
    }

    const int colb = blockIdx.x*128 + tx*8;
    float bv[8];
#pragma unroll
    for (int j=0;j<8;j++) bv[j] = bias1[colb+j] + (bias2 ? bias2[colb+j] : 0.f);
    const size_t rowb = (size_t)blockIdx.y*128 + ty*8;
#pragma unroll
    for (int i=0;i<4;i++){
        float v0[8], v1[8];
#pragma unroll
        for (int j=0;j<8;j++){
            float x0,x1; unpack2(acc[i][j],x0,x1);
            x0+=bv[j]; x1+=bv[j];
            if (ACT==1){ x0 = x0/(1.f+expf(-x0)); x1 = x1/(1.f+expf(-x1)); }
            v0[j]=x0; v1[j]=x1;
        }
        float* c0 = C + (rowb + 2*i)*(size_t)N + colb;
        float* c1 = c0 + N;
        __stcg((float4*)(c0),   make_float4(v0[0],v0[1],v0[2],v0[3]));
        __stcg((float4*)(c0+4), make_float4(v0[4],v0[5],v0[6],v0[7]));
        __stcg((float4*)(c1),   make_float4(v1[0],v1[1],v1[2],v1[3]));
        __stcg((float4*)(c1+4), make_float4(v1[4],v1[5],v1[6],v1[7]));
    }
}

__global__ void init_kernel(const float* __restrict__ hxs)
{
    if (blockIdx.x==0 && threadIdx.x==0){ g_arrive=0u; g_release=0u; }
    size_t i = (size_t)blockIdx.x*256 + threadIdx.x;
    ((float4*)g_h[0])[i] = ((const float4*)hxs)[i];
}

// ================= Persistent LSTM =================
// 128 blocks = 4 b-tiles(32 rows) x 32 h-tiles(16 h), 256 threads.
// Weights (128KB/CTA) L1-resident via __ldg (no fences -> no IVALL).
// h & xg staged cooperatively into smem (__ldcv / __ldcg). FFMA2 dot products.
// Barrier: atom.acq_rel arrive + ld.acquire poll. Streaming outputs via __stcg.
#define HS_STRIDE 516
__global__ __launch_bounds__(256)
void lstm_kernel(const float* __restrict__ Whh, const float* __restrict__ cxs,
                 float* __restrict__ dout)
{
    extern __shared__ __align__(16) float smem[];
    float* hsm = smem;                        // 32 rows x HS_STRIDE (66,048B)
    float* xsm = hsm + 32*HS_STRIDE;          // 32 x 4 x 16 (8KB)
    float* STb = xsm + 32*64;                 // 5 x 32 x 16 (10KB)
#define ST(a,r,q) STb[(((a)*32+(r))*16)+(q)]
    const int tid = threadIdx.x;
    const int b0 = (blockIdx.x & 3) * 32;
    const int hbase = (blockIdx.x >> 2) * 16;
    const int hloc = tid >> 4;        // 0..15
    const int bg = tid & 15;          // 0..15 -> 2 b rows
    const int h = hbase + hloc;
    const int rA = bg*2, rB = rA+1;
    const int bA = b0+rA, bB = b0+rB;

    const float* w0 = Whh + (size_t)(0*HHD + h)*HHD;
    const float* w1 = Whh + (size_t)(1*HHD + h)*HHD;
    const float* w2 = Whh + (size_t)(2*HHD + h)*HHD;
    const float* w3 = Whh + (size_t)(3*HHD + h)*HHD;
    const float* hrowA = hsm + rA*HS_STRIDE;
    const float* hrowB = hsm + rB*HS_STRIDE;

    float cA = cxs[(size_t)bA*HHD + h];
    float cB = cxs[(size_t)bB*HHD + h];

    float* outb = g_enc1;
    float* gp1 = dout + OFF_IG;  float* gp2 = dout + OFF_FG;
    float* gp3 = dout + OFF_GG;  float* gp4 = dout + OFF_OG;

    for (int t=0;t<TT;t++){
        const float* hin = g_h[t&1];
        float* hnx = g_h[(t+1)&1];

        // stage h tile (32 x 512) via ldcv (must see remote SM writes)
#pragma unroll
        for (int l=tid;l<4096;l+=256){
            int r = l>>7, c4 = (l&127)<<2;
            float4 v = __ldcv((const float4*)(hin + (size_t)(b0+r)*HHD + c4));
            *(float4*)&hsm[r*HS_STRIDE + c4] = v;
        }
        // stage xg tile (32 rows x 4 gates x 16 h) coalesced
#pragma unroll
        for (int l=tid;l<512;l+=256){
            int r = l>>4, rem = l&15, g = rem>>2, q4 = (rem&3)<<2;
            float4 v = __ldcg((const float4*)(g_xg + ((size_t)(b0+r)*TT + t)*G4 + (size_t)g*HHD + hbase + q4));
            *(float4*)&xsm[r*64 + g*16 + q4] = v;
        }
        __syncthreads();

        unsigned long long A0=0,A1=0,A2=0,A3=0,B0=0,B1=0,B2=0,B3=0;
#pragma unroll 4
        for (int k=0;k<HHD;k+=4){
            ulonglong2 wa = __ldg((const ulonglong2*)(w0+k));
            ulonglong2 wb = __ldg((const ulonglong2*)(w1+k));
            ulonglong2 wc = __ldg((const ulonglong2*)(w2+k));
            ulonglong2 wd = __ldg((const ulonglong2*)(w3+k));
            ulonglong2 hA = *(const ulonglong2*)(hrowA+k);
            ulonglong2 hB = *(const ulonglong2*)(hrowB+k);
            fma2(A0,hA.x,wa.x); fma2(A0,hA.y,wa.y);
            fma2(A1,hA.x,wb.x); fma2(A1,hA.y,wb.y);
            fma2(A2,hA.x,wc.x); fma2(A2,hA.y,wc.y);
            fma2(A3,hA.x,wd.x); fma2(A3,hA.y,wd.y);
            fma2(B0,hB.x,wa.x); fma2(B0,hB.y,wa.y);
            fma2(B1,hB.x,wb.x); fma2(B1,hB.y,wb.y);
            fma2(B2,hB.x,wc.x); fma2(B2,hB.y,wc.y);
            fma2(B3,hB.x,wd.x); fma2(B3,hB.y,wd.y);
        }
        float a0,a0h,a1,a1h,a2,a2h,a3,a3h,d0,d0h,d1,d1h,d2,d2h,d3,d3h;
        unpack2(A0,a0,a0h); unpack2(A1,a1,a1h); unpack2(A2,a2,a2h); unpack2(A3,a3,a3h);
        unpack2(B0,d0,d0h); unpack2(B1,d1,d1h); unpack2(B2,d2,d2h); unpack2(B3,d3,d3h);
        a0+=a0h; a1+=a1h; a2+=a2h; a3+=a3h;
        d0+=d0h; d1+=d1h; d2+=d2h; d3+=d3h;

        float iA = sigf(a0 + xsm[rA*64 + 0*16 + hloc]);
        float fA = sigf(a1 + xsm[rA*64 + 1*16 + hloc]);
        float gA = tanhf(a2 + xsm[rA*64 + 2*16 + hloc]);
        float oA = sigf(a3 + xsm[rA*64 + 3*16 + hloc]);
        float iB = sigf(d0 + xsm[rB*64 + 0*16 + hloc]);
        float fB = sigf(d1 + xsm[rB*64 + 1*16 + hloc]);
        float gB = tanhf(d2 + xsm[rB*64 + 2*16 + hloc]);
        float oB = sigf(d3 + xsm[rB*64 + 3*16 + hloc]);
        cA = fA*cA + iA*gA;  cB = fB*cB + iB*gB;
        float hAo = oA*tanhf(cA), hBo = oB*tanhf(cB);

        __syncthreads();   // done reading hsm/xsm this step
        ST(0,rA,hloc)=hAo; ST(0,rB,hloc)=hBo;
        ST(1,rA,hloc)=iA;  ST(1,rB,hloc)=iB;
        ST(2,rA,hloc)=fA;  ST(2,rB,hloc)=fB;
        ST(3,rA,hloc)=gA;  ST(3,rB,hloc)=gB;
        ST(4,rA,hloc)=oA;  ST(4,rB,hloc)=oB;
        __syncthreads();

        // h: 128 float4 slots; gates: 1024 float2 slots (gate sections of d_out
        // are only 8B-aligned: OFF_IG*4 == 8 mod 16). Streaming stores.
        for (int l=tid;l<1152;l+=256){
            if (l < 128){
                int r = l>>2, q4 = (l&3)<<2;
                float4 v = *(const float4*)&ST(0,r,q4);
                __stcg((float4*)(hnx + (size_t)(b0+r)*HHD + hbase + q4), v);
                __stcg((float4*)(outb + ((size_t)(b0+r)*TT + t)*HHD + hbase + q4), v);
            } else {
                int m = l - 128;
                int a = m >> 8;
                int r = (m >> 3) & 31;
                int q2 = (m & 7) << 1;
                float2 v = *(const float2*)&ST(a+1,r,q2);
                size_t base = ((size_t)(b0+r)*TT + t)*HHD + hbase + q2;
                float* gp = (a==0) ? gp1 : (a==1) ? gp2 : (a==2) ? gp3 : gp4;
                __stcg((float2*)(gp + base), v);
            }
        }

        if (t==TT-1){
            dout[OFF_HT + (size_t)bA*HHD + h] = hAo;
            dout[OFF_HT + (size_t)bB*HHD + h] = hBo;
            dout[OFF_CT + (size_t)bA*HHD + h] = cA;
            dout[OFF_CT + (size_t)bB*HHD + h] = cB;
        }

        __syncthreads();   // all stores (incl. hnx) issued before arrive
        if (tid==0){
            unsigned v;
            asm volatile("atom.acq_rel.gpu.global.add.u32 %0, [%1], %2;"
                         : "=r"(v) : "l"(&g_arrive), "r"(1u) : "memory");
            if (v == 127u){
                g_arrive = 0u;
                asm volatile("st.release.gpu.global.u32 [%0], %1;"
                             :: "l"(&g_release), "r"((unsigned)(t+1)) : "memory");
            } else {
                unsigned r;
                do {
                    asm volatile("ld.acquire.gpu.global.u32 %0, [%1];"
                                 : "=r"(r) : "l"(&g_release) : "memory");
                } while (r < (unsigned)(t+1));
            }
        }
        __syncthreads();
    }
#undef ST
}

__global__ __launch_bounds__(256)
void head_kernel(const float* __restrict__ Wa, const float* __restrict__ ba,
                 const float* __restrict__ Wc, const float* __restrict__ bc,
                 float* __restrict__ dout)
{
    __shared__ __align__(16) float xsr[16][516];
    const int tid = threadIdx.x;
    const size_t m0 = (size_t)blockIdx.x * 16;
    for (int l=tid;l<2048;l+=256){
        int r=l>>7, c4=(l&127)<<2;
        *(float4*)&xsr[r][c4] = *(const float4*)(g_enc1 + (m0+r)*HHD + c4);
    }
    __syncthreads();
    for (int o=tid;o<16*19;o+=256){
        int r=o/19, n=o-r*19;
        const float* wrow = (n<18) ? (Wa + (size_t)n*HHD) : Wc;
        float acc=0.f;
#pragma unroll 4
        for (int k=0;k<HHD;k+=4){
            float4 w = __ldg((const float4*)(wrow+k));
            float4 x = *(const float4*)&xsr[r][k];
            acc += x.x*w.x + x.y*w.y + x.z*w.z + x.w*w.w;
        }
        size_t m = m0 + r;
        if (n<18) dout[OFF_LOGITS + m*AA + n] = acc + ba[n];
        else      dout[OFF_VALUES + m] = acc + bc[0];
    }
}

__global__ __launch_bounds__(256)
void loss_partial()
{
    float s1=0.f, s2=0.f;
    const size_t n = (size_t)MM*HHD;
    for (size_t i=(size_t)blockIdx.x*256+threadIdx.x; i<n; i+=(size_t)LOSS_BLOCKS*256){
        float x = g_enc1[i];
        s1 += x*x;
        unsigned t = ((unsigned)(i>>9)) & 511u;
        if (t != 511u){ float d = g_enc1[i+512] - x; s2 += d*d; }
    }
    __shared__ double r1[256], r2[256];
    r1[threadIdx.x]=(double)s1; r2[threadIdx.x]=(double)s2;
    __syncthreads();
    for (int s=128;s>0;s>>=1){
        if (threadIdx.x<s){ r1[threadIdx.x]+=r1[threadIdx.x+s]; r2[threadIdx.x]+=r2[threadIdx.x+s]; }
        __syncthreads();
    }
    if (threadIdx.x==0){ g_part[0][blockIdx.x]=r1[0]; g_part[1][blockIdx.x]=r2[0]; }
}

__global__ void loss_final(float* __restrict__ dout)
{
    __shared__ double r1[256], r2[256];
    double s1=0.0, s2=0.0;
    for (int i=threadIdx.x;i<LOSS_BLOCKS;i+=256){ s1+=g_part[0][i]; s2+=g_part[1][i]; }
    r1[threadIdx.x]=s1; r2[threadIdx.x]=s2;
    __syncthreads();
    for (int s=128;s>0;s>>=1){
        if (threadIdx.x<s){ r1[threadIdx.x]+=r1[threadIdx.x+s]; r2[threadIdx.x]+=r2[threadIdx.x+s]; }
        __syncthreads();
    }
    if (threadIdx.x==0){
        dout[OFF_AR]  = (float)(r1[0] * (0.01 / ((double)MM * HHD)));
        dout[OFF_TAR] = (float)(r2[0] * (0.01 / ((double)BB * (TT-1) * HHD)));
    }
}

extern "C" void kernel_launch(void* const* d_in, const int* in_sizes, int n_in,
                              void* d_out, int out_size)
{
    const float* obs  = (const float*)d_in[0];
    const float* hxs  = (const float*)d_in[1];
    const float* cxs  = (const float*)d_in[2];
    const float* W1   = (const float*)d_in[3];
    const float* b1   = (const float*)d_in[4];
    const float* W2   = (const float*)d_in[5];
    const float* b2   = (const float*)d_in[6];
    const float* W_ih = (const float*)d_in[7];
    const float* W_hh = (const float*)d_in[8];
    const float* b_ih = (const float*)d_in[9];
    const float* b_hh = (const float*)d_in[10];
    const float* Wa   = (const float*)d_in[11];
    const float* ba   = (const float*)d_in[12];
    const float* Wc   = (const float*)d_in[13];
    const float* bc   = (const float*)d_in[14];
    float* dout = (float*)d_out;

    float* enc1; cudaGetSymbolAddress((void**)&enc1, g_enc1);
    float* enc2; cudaGetSymbolAddress((void**)&enc2, g_enc2);
    float* xg;   cudaGetSymbolAddress((void**)&xg,   g_xg);

    const int lstm_smem = (32*HS_STRIDE + 32*64 + 5*32*16) * (int)sizeof(float);
    cudaFuncSetAttribute(lstm_kernel, cudaFuncAttributeMaxDynamicSharedMemorySize, lstm_smem);

    init_kernel<<<64, 256>>>(hxs);   // first, so ncu skip-5 lands on gemm3
    // enc1 = silu(obs @ W1^T + b1)   [65536 x 512, K=128]
    gemm_nt<1><<<dim3(ENC/128, MM/128), 256>>>(obs, W1, b1, nullptr, enc1, 128, ENC);
    // enc2 = silu(enc1 @ W2^T + b2)  [65536 x 512, K=512]
    gemm_nt<1><<<dim3(ENC/128, MM/128), 256>>>(enc1, W2, b2, nullptr, enc2, ENC, ENC);
    // xg = enc2 @ W_ih^T + b_ih + b_hh   [65536 x 2048, K=512]
    gemm_nt<0><<<dim3(G4/128, MM/128), 256>>>(enc2, W_ih, b_ih, b_hh, xg, ENC, G4);

    lstm_kernel<<<128, 256, lstm_smem>>>(W_hh, cxs, dout);
    head_kernel<<<MM/16, 256>>>(Wa, ba, Wc, bc, dout);
    loss_partial<<<LOSS_BLOCKS, 256>>>();
    loss_final<<<1, 256>>>(dout);
}

// round 6
// speedup vs baseline: 2.0559x; 1.0443x over previous
#include <cuda_runtime.h>
#include <math.h>

#define BB 128
#define TT 512
#define ENC 512
#define HHD 512
#define AA 18
#define MM (BB*TT)
#define G4 (4*HHD)

#define N_LOGITS ((size_t)MM*AA)
#define OFF_LOGITS ((size_t)0)
#define OFF_VALUES (N_LOGITS)
#define OFF_HT (OFF_VALUES + (size_t)MM)
#define OFF_CT (OFF_HT + (size_t)BB*HHD)
#define OFF_AR (OFF_CT + (size_t)BB*HHD)
#define OFF_TAR (OFF_AR + 1)
#define NGATE ((size_t)MM*HHD)
#define OFF_IG (OFF_TAR + 1)
#define OFF_FG (OFF_IG + NGATE)
#define OFF_GG (OFF_FG + NGATE)
#define OFF_OG (OFF_GG + NGATE)

__device__ __align__(16) float g_enc1[(size_t)MM*ENC];   // enc1; later reused as LSTM out (B,T,H)
__device__ __align__(16) float g_enc2[(size_t)MM*ENC];
__device__ __align__(16) float g_xg[(size_t)MM*G4];
__device__ __align__(16) float g_h[2][BB*HHD];
#define LOSS_BLOCKS 2048
__device__ double g_part[2][LOSS_BLOCKS];
__device__ unsigned g_arrive;
__device__ unsigned g_release;

__device__ __forceinline__ float sigf(float x){ return 1.f/(1.f+expf(-x)); }
__device__ __forceinline__ unsigned long long f2dup(float x){
    unsigned long long r; asm("mov.b64 %0, {%1, %1};" : "=l"(r) : "r"(__float_as_uint(x))); return r;
}
__device__ __forceinline__ void fma2(unsigned long long& d, unsigned long long a, unsigned long long b){
    asm("fma.rn.f32x2 %0, %1, %2, %0;" : "+l"(d) : "l"(a), "l"(b));
}
__device__ __forceinline__ void unpack2(unsigned long long v, float& lo, float& hi){
    unsigned l,h; asm("mov.b64 {%0, %1}, %2;" : "=r"(l), "=r"(h) : "l"(v));
    lo=__uint_as_float(l); hi=__uint_as_float(h);
}

// ================= GEMM (NT) =================
// C[m][n] = act(sum_k A[m][k]*B[n][k] + bias1[n] (+bias2[n]))
// BM=BN=128, BK=16, 256 threads, 8x8 thread tile.
// Natural smem layouts (A pairs along M via LDS.128; B dup'd in regs via MOV).
// Double-buffered smem, ONE __syncthreads per k-tile, LDG prefetch.
template<int ACT>
__global__ __launch_bounds__(256)
void gemm_nt(const float* __restrict__ A, const float* __restrict__ Bm,
             const float* __restrict__ bias1, const float* __restrict__ bias2,
             float* __restrict__ C, int K, int N)
{
    __shared__ __align__(16) float As[2][16][132];
    __shared__ __align__(16) float Bs[2][16][132];
    const int tid = threadIdx.x;
    const int tx = tid & 15, ty = tid >> 4;
    const float* Ab = A + (size_t)blockIdx.y * 128 * K;
    const float* Bb = Bm + (size_t)blockIdx.x * 128 * K;

    const int row0 = tid >> 2, c4 = (tid & 3) << 2;
    const int row1 = row0 + 64;

    unsigned long long acc[4][8];
#pragma unroll
    for (int i=0;i<4;i++)
#pragma unroll
        for (int j=0;j<8;j++) acc[i][j]=0ull;

    const int nk = K >> 4;
    // load tile 0 into buf 0
    {
        float4 a0 = __ldcg((const float4*)(Ab + (size_t)row0*K + c4));
        float4 b0 = __ldcg((const float4*)(Bb + (size_t)row0*K + c4));
        float4 a1 = __ldcg((const float4*)(Ab + (size_t)row1*K + c4));
        float4 b1 = __ldcg((const float4*)(Bb + (size_t)row1*K + c4));
        As[0][c4+0][row0]=a0.x; As[0][c4+1][row0]=a0.y; As[0][c4+2][row0]=a0.z; As[0][c4+3][row0]=a0.w;
        Bs[0][c4+0][row0]=b0.x; Bs[0][c4+1][row0]=b0.y; Bs[0][c4+2][row0]=b0.z; Bs[0][c4+3][row0]=b0.w;
        As[0][c4+0][row1]=a1.x; As[0][c4+1][row1]=a1.y; As[0][c4+2][row1]=a1.z; As[0][c4+3][row1]=a1.w;
        Bs[0][c4+0][row1]=b1.x; Bs[0][c4+1][row1]=b1.y; Bs[0][c4+2][row1]=b1.z; Bs[0][c4+3][row1]=b1.w;
    }
    __syncthreads();

    int buf = 0;
    for (int kt=0; kt<nk; kt++){
        float4 pa0, pb0, pa1, pb1;
        const bool more = (kt+1 < nk);
        if (more){
            int k0 = (kt+1) << 4;
            pa0 = __ldcg((const float4*)(Ab + (size_t)row0*K + k0 + c4));
            pb0 = __ldcg((const float4*)(Bb + (size_t)row0*K + k0 + c4));
            pa1 = __ldcg((const float4*)(Ab + (size_t)row1*K + k0 + c4));
            pb1 = __ldcg((const float4*)(Bb + (size_t)row1*K + k0 + c4));
        }
#pragma unroll
        for (int kk=0;kk<16;kk++){
            ulonglong2 ua = *(const ulonglong2*)&As[buf][kk][ty*8];
            ulonglong2 ub = *(const ulonglong2*)&As[buf][kk][ty*8+4];
            unsigned long long ap[4] = { ua.x, ua.y, ub.x, ub.y };
            float4 f0 = *(const float4*)&Bs[buf][kk][tx*8];
            float4 f1 = *(const float4*)&Bs[buf][kk][tx*8+4];
            unsigned long long bd[8] = { f2dup(f0.x),f2dup(f0.y),f2dup(f0.z),f2dup(f0.w),
                                         f2dup(f1.x),f2dup(f1.y),f2dup(f1.z),f2dup(f1.w) };
#pragma unroll
            for (int i=0;i<4;i++)
#pragma unroll
                for (int j=0;j<8;j++) fma2(acc[i][j], ap[i], bd[j]);
        }
        if (more){
            int nb = buf ^ 1;
            As[nb][c4+0][row0]=pa0.x; As[nb][c4+1][row0]=pa0.y; As[nb][c4+2][row0]=pa0.z; As[nb][c4+3][row0]=pa0.w;
            Bs[nb][c4+0][row0]=pb0.x; Bs[nb][c4+1][row0]=pb0.y; Bs[nb][c4+2][row0]=pb0.z; Bs[nb][c4+3][row0]=pb0.w;
            As[nb][c4+0][row1]=pa1.x; As[nb][c4+1][row1]=pa1.y; As[nb][c4+2][row1]=pa1.z; As[nb][c4+3][row1]=pa1.w;
            Bs[nb][c4+0][row1]=pb1.x; Bs[nb][c4+1][row1]=pb1.y; Bs[nb][c4+2][row1]=pb1.z; Bs[nb][c4+3][row1]=pb1.w;
            __syncthreads();
            buf = nb;
        }
    }

    const int colb = blockIdx.x*128 + tx*8;
    float bv[8];
#pragma unroll
    for (int j=0;j<8;j++) bv[j] = bias1[colb+j] + (bias2 ? bias2[colb+j] : 0.f);
    const size_t rowb = (size_t)blockIdx.y*128 + ty*8;
#pragma unroll
    for (int i=0;i<4;i++){
        float v0[8], v1[8];
#pragma unroll
        for (int j=0;j<8;j++){
            float x0,x1; unpack2(acc[i][j],x0,x1);
            x0+=bv[j]; x1+=bv[j];
            if (ACT==1){ x0 = x0/(1.f+expf(-x0)); x1 = x1/(1.f+expf(-x1)); }
            v0[j]=x0; v1[j]=x1;
        }
        float* c0 = C + (rowb + 2*i)*(size_t)N + colb;
        float* c1 = c0 + N;
        __stcg((float4*)(c0),   make_float4(v0[0],v0[1],v0[2],v0[3]));
        __stcg((float4*)(c0+4), make_float4(v0[4],v0[5],v0[6],v0[7]));
        __stcg((float4*)(c1),   make_float4(v1[0],v1[1],v1[2],v1[3]));
        __stcg((float4*)(c1+4), make_float4(v1[4],v1[5],v1[6],v1[7]));
    }
}

__global__ void init_kernel(const float* __restrict__ hxs)
{
    if (blockIdx.x==0 && threadIdx.x==0){ g_arrive=0u; g_release=0u; }
    size_t i = (size_t)blockIdx.x*256 + threadIdx.x;
    ((float4*)g_h[0])[i] = ((const float4*)hxs)[i];
}

// ================= Persistent LSTM =================
// 128 blocks = 4 b-tiles(32 rows) x 32 h-tiles(16 h), 256 threads.
// Weights (128KB/CTA) L1-resident via __ldg (no fences -> no IVALL).
// h & xg staged cooperatively into smem (__ldcv / __ldcg). FFMA2 dot products.
// Barrier: atom.acq_rel arrive + ld.acquire poll. Streaming outputs via __stcg.
#define HS_STRIDE 516
__global__ __launch_bounds__(256)
void lstm_kernel(const float* __restrict__ Whh, const float* __restrict__ cxs,
                 float* __restrict__ dout)
{
    extern __shared__ __align__(16) float smem[];
    float* hsm = smem;                        // 32 rows x HS_STRIDE (66,048B)
    float* xsm = hsm + 32*HS_STRIDE;          // 32 x 4 x 16 (8KB)
    float* STb = xsm + 32*64;                 // 5 x 32 x 16 (10KB)
#define ST(a,r,q) STb[(((a)*32+(r))*16)+(q)]
    const int tid = threadIdx.x;
    const int b0 = (blockIdx.x & 3) * 32;
    const int hbase = (blockIdx.x >> 2) * 16;
    const int hloc = tid >> 4;        // 0..15
    const int bg = tid & 15;          // 0..15 -> 2 b rows
    const int h = hbase + hloc;
    const int rA = bg*2, rB = rA+1;
    const int bA = b0+rA, bB = b0+rB;

    const float* w0 = Whh + (size_t)(0*HHD + h)*HHD;
    const float* w1 = Whh + (size_t)(1*HHD + h)*HHD;
    const float* w2 = Whh + (size_t)(2*HHD + h)*HHD;
    const float* w3 = Whh + (size_t)(3*HHD + h)*HHD;
    const float* hrowA = hsm + rA*HS_STRIDE;
    const float* hrowB = hsm + rB*HS_STRIDE;

    float cA = cxs[(size_t)bA*HHD + h];
    float cB = cxs[(size_t)bB*HHD + h];

    float* outb = g_enc1;
    float* gp1 = dout + OFF_IG;  float* gp2 = dout + OFF_FG;
    float* gp3 = dout + OFF_GG;  float* gp4 = dout + OFF_OG;

    for (int t=0;t<TT;t++){
        const float* hin = g_h[t&1];
        float* hnx = g_h[(t+1)&1];

        // stage h tile (32 x 512) via ldcv (must see remote SM writes)
#pragma unroll
        for (int l=tid;l<4096;l+=256){
            int r = l>>7, c4 = (l&127)<<2;
            float4 v = __ldcv((const float4*)(hin + (size_t)(b0+r)*HHD + c4));
            *(float4*)&hsm[r*HS_STRIDE + c4] = v;
        }
        // stage xg tile (32 rows x 4 gates x 16 h) coalesced
#pragma unroll
        for (int l=tid;l<512;l+=256){
            int r = l>>4, rem = l&15, g = rem>>2, q4 = (rem&3)<<2;
            float4 v = __ldcg((const float4*)(g_xg + ((size_t)(b0+r)*TT + t)*G4 + (size_t)g*HHD + hbase + q4));
            *(float4*)&xsm[r*64 + g*16 + q4] = v;
        }
        __syncthreads();

        unsigned long long A0=0,A1=0,A2=0,A3=0,B0=0,B1=0,B2=0,B3=0;
#pragma unroll 4
        for (int k=0;k<HHD;k+=4){
            ulonglong2 wa = __ldg((const ulonglong2*)(w0+k));
            ulonglong2 wb = __ldg((const ulonglong2*)(w1+k));
            ulonglong2 wc = __ldg((const ulonglong2*)(w2+k));
            ulonglong2 wd = __ldg((const ulonglong2*)(w3+k));
            ulonglong2 hA = *(const ulonglong2*)(hrowA+k);
            ulonglong2 hB = *(const ulonglong2*)(hrowB+k);
            fma2(A0,hA.x,wa.x); fma2(A0,hA.y,wa.y);
            fma2(A1,hA.x,wb.x); fma2(A1,hA.y,wb.y);
            fma2(A2,hA.x,wc.x); fma2(A2,hA.y,wc.y);
            fma2(A3,hA.x,wd.x); fma2(A3,hA.y,wd.y);
            fma2(B0,hB.x,wa.x); fma2(B0,hB.y,wa.y);
            fma2(B1,hB.x,wb.x); fma2(B1,hB.y,wb.y);
            fma2(B2,hB.x,wc.x); fma2(B2,hB.y,wc.y);
            fma2(B3,hB.x,wd.x); fma2(B3,hB.y,wd.y);
        }
        float a0,a0h,a1,a1h,a2,a2h,a3,a3h,d0,d0h,d1,d1h,d2,d2h,d3,d3h;
        unpack2(A0,a0,a0h); unpack2(A1,a1,a1h); unpack2(A2,a2,a2h); unpack2(A3,a3,a3h);
        unpack2(B0,d0,d0h); unpack2(B1,d1,d1h); unpack2(B2,d2,d2h); unpack2(B3,d3,d3h);
        a0+=a0h; a1+=a1h; a2+=a2h; a3+=a3h;
        d0+=d0h; d1+=d1h; d2+=d2h; d3+=d3h;

        float iA = sigf(a0 + xsm[rA*64 + 0*16 + hloc]);
        float fA = sigf(a1 + xsm[rA*64 + 1*16 + hloc]);
        float gA = tanhf(a2 + xsm[rA*64 + 2*16 + hloc]);
        float oA = sigf(a3 + xsm[rA*64 + 3*16 + hloc]);
        float iB = sigf(d0 + xsm[rB*64 + 0*16 + hloc]);
        float fB = sigf(d1 + xsm[rB*64 + 1*16 + hloc]);
        float gB = tanhf(d2 + xsm[rB*64 + 2*16 + hloc]);
        float oB = sigf(d3 + xsm[rB*64 + 3*16 + hloc]);
        cA = fA*cA + iA*gA;  cB = fB*cB + iB*gB;
        float hAo = oA*tanhf(cA), hBo = oB*tanhf(cB);

        __syncthreads();   // done reading hsm/xsm this step
        ST(0,rA,hloc)=hAo; ST(0,rB,hloc)=hBo;
        ST(1,rA,hloc)=iA;  ST(1,rB,hloc)=iB;
        ST(2,rA,hloc)=fA;  ST(2,rB,hloc)=fB;
        ST(3,rA,hloc)=gA;  ST(3,rB,hloc)=gB;
        ST(4,rA,hloc)=oA;  ST(4,rB,hloc)=oB;
        __syncthreads();

        // h: 128 float4 slots; gates: 1024 float2 slots (gate sections of d_out
        // are only 8B-aligned: OFF_IG*4 == 8 mod 16). Streaming stores.
        for (int l=tid;l<1152;l+=256){
            if (l < 128){
                int r = l>>2, q4 = (l&3)<<2;
                float4 v = *(const float4*)&ST(0,r,q4);
                __stcg((float4*)(hnx + (size_t)(b0+r)*HHD + hbase + q4), v);
                __stcg((float4*)(outb + ((size_t)(b0+r)*TT + t)*HHD + hbase + q4), v);
            } else {
                int m = l - 128;
                int a = m >> 8;
                int r = (m >> 3) & 31;
                int q2 = (m & 7) << 1;
                float2 v = *(const float2*)&ST(a+1,r,q2);
                size_t base = ((size_t)(b0+r)*TT + t)*HHD + hbase + q2;
                float* gp = (a==0) ? gp1 : (a==1) ? gp2 : (a==2) ? gp3 : gp4;
                __stcg((float2*)(gp + base), v);
            }
        }

        if (t==TT-1){
            dout[OFF_HT + (size_t)bA*HHD + h] = hAo;
            dout[OFF_HT + (size_t)bB*HHD + h] = hBo;
            dout[OFF_CT + (size_t)bA*HHD + h] = cA;
            dout[OFF_CT + (size_t)bB*HHD + h] = cB;
        }

        __syncthreads();   // all stores (incl. hnx) issued before arrive
        if (tid==0){
            unsigned v;
            asm volatile("atom.acq_rel.gpu.global.add.u32 %0, [%1], %2;"
                         : "=r"(v) : "l"(&g_arrive), "r"(1u) : "memory");
            if (v == 127u){
                g_arrive = 0u;
                asm volatile("st.release.gpu.global.u32 [%0], %1;"
                             :: "l"(&g_release), "r"((unsigned)(t+1)) : "memory");
            } else {
                unsigned r;
                do {
                    asm volatile("ld.acquire.gpu.global.u32 %0, [%1];"
                                 : "=r"(r) : "l"(&g_release) : "memory");
                } while (r < (unsigned)(t+1));
            }
        }
        __syncthreads();
    }
#undef ST
}

__global__ __launch_bounds__(256)
void head_kernel(const float* __restrict__ Wa, const float* __restrict__ ba,
                 const float* __restrict__ Wc, const float* __restrict__ bc,
                 float* __restrict__ dout)
{
    __shared__ __align__(16) float xsr[16][516];
    const int tid = threadIdx.x;
    const size_t m0 = (size_t)blockIdx.x * 16;
    for (int l=tid;l<2048;l+=256){
        int r=l>>7, c4=(l&127)<<2;
        *(float4*)&xsr[r][c4] = *(const float4*)(g_enc1 + (m0+r)*HHD + c4);
    }
    __syncthreads();
    for (int o=tid;o<16*19;o+=256){
        int r=o/19, n=o-r*19;
        const float* wrow = (n<18) ? (Wa + (size_t)n*HHD) : Wc;
        float acc=0.f;
#pragma unroll 4
        for (int k=0;k<HHD;k+=4){
            float4 w = __ldg((const float4*)(wrow+k));
            float4 x = *(const float4*)&xsr[r][k];
            acc += x.x*w.x + x.y*w.y + x.z*w.z + x.w*w.w;
        }
        size_t m = m0 + r;
        if (n<18) dout[OFF_LOGITS + m*AA + n] = acc + ba[n];
        else      dout[OFF_VALUES + m] = acc + bc[0];
    }
}

__global__ __launch_bounds__(256)
void loss_partial()
{
    float s1=0.f, s2=0.f;
    const size_t n = (size_t)MM*HHD;
    for (size_t i=(size_t)blockIdx.x*256+threadIdx.x; i<n; i+=(size_t)LOSS_BLOCKS*256){
        float x = g_enc1[i];
        s1 += x*x;
        unsigned t = ((unsigned)(i>>9)) & 511u;
        if (t != 511u){ float d = g_enc1[i+512] - x; s2 += d*d; }
    }
    __shared__ double r1[256], r2[256];
    r1[threadIdx.x]=(double)s1; r2[threadIdx.x]=(double)s2;
    __syncthreads();
    for (int s=128;s>0;s>>=1){
        if (threadIdx.x<s){ r1[threadIdx.x]+=r1[threadIdx.x+s]; r2[threadIdx.x]+=r2[threadIdx.x+s]; }
        __syncthreads();
    }
    if (threadIdx.x==0){ g_part[0][blockIdx.x]=r1[0]; g_part[1][blockIdx.x]=r2[0]; }
}

__global__ void loss_final(float* __restrict__ dout)
{
    __shared__ double r1[256], r2[256];
    double s1=0.0, s2=0.0;
    for (int i=threadIdx.x;i<LOSS_BLOCKS;i+=256){ s1+=g_part[0][i]; s2+=g_part[1][i]; }
    r1[threadIdx.x]=s1; r2[threadIdx.x]=s2;
    __syncthreads();
    for (int s=128;s>0;s>>=1){
        if (threadIdx.x<s){ r1[threadIdx.x]+=r1[threadIdx.x+s]; r2[threadIdx.x]+=r2[threadIdx.x+s]; }
        __syncthreads();
    }
    if (threadIdx.x==0){
        dout[OFF_AR]  = (float)(r1[0] * (0.01 / ((double)MM * HHD)));
        dout[OFF_TAR] = (float)(r2[0] * (0.01 / ((double)BB * (TT-1) * HHD)));
    }
}

extern "C" void kernel_launch(void* const* d_in, const int* in_sizes, int n_in,
                              void* d_out, int out_size)
{
    const float* obs  = (const float*)d_in[0];
    const float* hxs  = (const float*)d_in[1];
    const float* cxs  = (const float*)d_in[2];
    const float* W1   = (const float*)d_in[3];
    const float* b1   = (const float*)d_in[4];
    const float* W2   = (const float*)d_in[5];
    const float* b2   = (const float*)d_in[6];
    const float* W_ih = (const float*)d_in[7];
    const float* W_hh = (const float*)d_in[8];
    const float* b_ih = (const float*)d_in[9];
    const float* b_hh = (const float*)d_in[10];
    const float* Wa   = (const float*)d_in[11];
    const float* ba   = (const float*)d_in[12];
    const float* Wc   = (const float*)d_in[13];
    const float* bc   = (const float*)d_in[14];
    float* dout = (float*)d_out;

    float* enc1; cudaGetSymbolAddress((void**)&enc1, g_enc1);
    float* enc2; cudaGetSymbolAddress((void**)&enc2, g_enc2);
    float* xg;   cudaGetSymbolAddress((void**)&xg,   g_xg);

    const int lstm_smem = (32*HS_STRIDE + 32*64 + 5*32*16) * (int)sizeof(float);
    cudaFuncSetAttribute(lstm_kernel, cudaFuncAttributeMaxDynamicSharedMemorySize, lstm_smem);

    init_kernel<<<64, 256>>>(hxs);   // first, so ncu skip-5 lands on gemm3
    // enc1 = silu(obs @ W1^T + b1)   [65536 x 512, K=128]
    gemm_nt<1><<<dim3(ENC/128, MM/128), 256>>>(obs, W1, b1, nullptr, enc1, 128, ENC);
    // enc2 = silu(enc1 @ W2^T + b2)  [65536 x 512, K=512]
    gemm_nt<1><<<dim3(ENC/128, MM/128), 256>>>(enc1, W2, b2, nullptr, enc2, ENC, ENC);
    // xg = enc2 @ W_ih^T + b_ih + b_hh   [65536 x 2048, K=512]
    gemm_nt<0><<<dim3(G4/128, MM/128), 256>>>(enc2, W_ih, b_ih, b_hh, xg, ENC, G4);

    lstm_kernel<<<128, 256, lstm_smem>>>(W_hh, cxs, dout);
    head_kernel<<<MM/16, 256>>>(Wa, ba, Wc, bc, dout);
    loss_partial<<<LOSS_BLOCKS, 256>>>();
    loss_final<<<1, 256>>>(dout);
}

// round 7
// speedup vs baseline: 2.0610x; 1.0025x over previous
#include <cuda_runtime.h>
#include <math.h>

#define BB 128
#define TT 512
#define ENC 512
#define HHD 512
#define AA 18
#define MM (BB*TT)
#define G4 (4*HHD)

#define N_LOGITS ((size_t)MM*AA)
#define OFF_LOGITS ((size_t)0)
#define OFF_VALUES (N_LOGITS)
#define OFF_HT (OFF_VALUES + (size_t)MM)
#define OFF_CT (OFF_HT + (size_t)BB*HHD)
#define OFF_AR (OFF_CT + (size_t)BB*HHD)
#define OFF_TAR (OFF_AR + 1)
#define NGATE ((size_t)MM*HHD)
#define OFF_IG (OFF_TAR + 1)
#define OFF_FG (OFF_IG + NGATE)
#define OFF_GG (OFF_FG + NGATE)
#define OFF_OG (OFF_GG + NGATE)

__device__ __align__(16) float g_enc1[(size_t)MM*ENC];   // enc1; later reused as LSTM out (B,T,H)
__device__ __align__(16) float g_enc2[(size_t)MM*ENC];
__device__ __align__(16) float g_xg[(size_t)MM*G4];
__device__ __align__(16) float g_h[2][BB*HHD];
#define LOSS_BLOCKS 2048
__device__ double g_part[2][LOSS_BLOCKS];
__device__ unsigned g_arrive;
__device__ unsigned g_release;

__device__ __forceinline__ float sigf(float x){ return 1.f/(1.f+expf(-x)); }
__device__ __forceinline__ unsigned long long f2dup(float x){
    unsigned long long r; asm("mov.b64 %0, {%1, %1};" : "=l"(r) : "r"(__float_as_uint(x))); return r;
}
__device__ __forceinline__ void fma2(unsigned long long& d, unsigned long long a, unsigned long long b){
    asm("fma.rn.f32x2 %0, %1, %2, %0;" : "+l"(d) : "l"(a), "l"(b));
}
__device__ __forceinline__ void unpack2(unsigned long long v, float& lo, float& hi){
    unsigned l,h; asm("mov.b64 {%0, %1}, %2;" : "=r"(l), "=r"(h) : "l"(v));
    lo=__uint_as_float(l); hi=__uint_as_float(h);
}

// ================= GEMM (NT) =================
// C[m][n] = act(sum_k A[m][k]*B[n][k] + bias1[n] (+bias2[n]))
// BM=BN=128, BK=16, 256 threads, 8x8 thread tile.
// Natural smem layouts (A pairs along M via LDS.128; B dup'd in regs via MOV).
// Double-buffered smem, ONE __syncthreads per k-tile, LDG prefetch.
template<int ACT>
__global__ __launch_bounds__(256)
void gemm_nt(const float* __restrict__ A, const float* __restrict__ Bm,
             const float* __restrict__ bias1, const float* __restrict__ bias2,
             float* __restrict__ C, int K, int N)
{
    __shared__ __align__(16) float As[2][16][132];
    __shared__ __align__(16) float Bs[2][16][132];
    const int tid = threadIdx.x;
    const int tx = tid & 15, ty = tid >> 4;
    const float* Ab = A + (size_t)blockIdx.y * 128 * K;
    const float* Bb = Bm + (size_t)blockIdx.x * 128 * K;

    const int row0 = tid >> 2, c4 = (tid & 3) << 2;
    const int row1 = row0 + 64;

    unsigned long long acc[4][8];
#pragma unroll
    for (int i=0;i<4;i++)
#pragma unroll
        for (int j=0;j<8;j++) acc[i][j]=0ull;

    const int nk = K >> 4;
    // load tile 0 into buf 0
    {
        float4 a0 = __ldcg((const float4*)(Ab + (size_t)row0*K + c4));
        float4 b0 = __ldcg((const float4*)(Bb + (size_t)row0*K + c4));
        float4 a1 = __ldcg((const float4*)(Ab + (size_t)row1*K + c4));
        float4 b1 = __ldcg((const float4*)(Bb + (size_t)row1*K + c4));
        As[0][c4+0][row0]=a0.x; As[0][c4+1][row0]=a0.y; As[0][c4+2][row0]=a0.z; As[0][c4+3][row0]=a0.w;
        Bs[0][c4+0][row0]=b0.x; Bs[0][c4+1][row0]=b0.y; Bs[0][c4+2][row0]=b0.z; Bs[0][c4+3][row0]=b0.w;
        As[0][c4+0][row1]=a1.x; As[0][c4+1][row1]=a1.y; As[0][c4+2][row1]=a1.z; As[0][c4+3][row1]=a1.w;
        Bs[0][c4+0][row1]=b1.x; Bs[0][c4+1][row1]=b1.y; Bs[0][c4+2][row1]=b1.z; Bs[0][c4+3][row1]=b1.w;
    }
    __syncthreads();

    int buf = 0;
    for (int kt=0; kt<nk; kt++){
        float4 pa0, pb0, pa1, pb1;
        const bool more = (kt+1 < nk);
        if (more){
            int k0 = (kt+1) << 4;
            pa0 = __ldcg((const float4*)(Ab + (size_t)row0*K + k0 + c4));
            pb0 = __ldcg((const float4*)(Bb + (size_t)row0*K + k0 + c4));
            pa1 = __ldcg((const float4*)(Ab + (size_t)row1*K + k0 + c4));
            pb1 = __ldcg((const float4*)(Bb + (size_t)row1*K + k0 + c4));
        }
#pragma unroll
        for (int kk=0;kk<16;kk++){
            ulonglong2 ua = *(const ulonglong2*)&As[buf][kk][ty*8];
            ulonglong2 ub = *(const ulonglong2*)&As[buf][kk][ty*8+4];
            unsigned long long ap[4] = { ua.x, ua.y, ub.x, ub.y };
            float4 f0 = *(const float4*)&Bs[buf][kk][tx*8];
            float4 f1 = *(const float4*)&Bs[buf][kk][tx*8+4];
            unsigned long long bd[8] = { f2dup(f0.x),f2dup(f0.y),f2dup(f0.z),f2dup(f0.w),
                                         f2dup(f1.x),f2dup(f1.y),f2dup(f1.z),f2dup(f1.w) };
#pragma unroll
            for (int i=0;i<4;i++)
#pragma unroll
                for (int j=0;j<8;j++) fma2(acc[i][j], ap[i], bd[j]);
        }
        if (more){
            int nb = buf ^ 1;
            As[nb][c4+0][row0]=pa0.x; As[nb][c4+1][row0]=pa0.y; As[nb][c4+2][row0]=pa0.z; As[nb][c4+3][row0]=pa0.w;
            Bs[nb][c4+0][row0]=pb0.x; Bs[nb][c4+1][row0]=pb0.y; Bs[nb][c4+2][row0]=pb0.z; Bs[nb][c4+3][row0]=pb0.w;
            As[nb][c4+0][row1]=pa1.x; As[nb][c4+1][row1]=pa1.y; As[nb][c4+2][row1]=pa1.z; As[nb][c4+3][row1]=pa1.w;
            Bs[nb][c4+0][row1]=pb1.x; Bs[nb][c4+1][row1]=pb1.y; Bs[nb][c4+2][row1]=pb1.z; Bs[nb][c4+3][row1]=pb1.w;
            __syncthreads();
            buf = nb;
        }
    }

    const int colb = blockIdx.x*128 + tx*8;
    float bv[8];
#pragma unroll
    for (int j=0;j<8;j++) bv[j] = bias1[colb+j] + (bias2 ? bias2[colb+j] : 0.f);
    const size_t rowb = (size_t)blockIdx.y*128 + ty*8;
#pragma unroll
    for (int i=0;i<4;i++){
        float v0[8], v1[8];
#pragma unroll
        for (int j=0;j<8;j++){
            float x0,x1; unpack2(acc[i][j],x0,x1);
            x0+=bv[j]; x1+=bv[j];
            if (ACT==1){ x0 = x0/(1.f+expf(-x0)); x1 = x1/(1.f+expf(-x1)); }
            v0[j]=x0; v1[j]=x1;
        }
        float* c0 = C + (rowb + 2*i)*(size_t)N + colb;
        float* c1 = c0 + N;
        __stcg((float4*)(c0),   make_float4(v0[0],v0[1],v0[2],v0[3]));
        __stcg((float4*)(c0+4), make_float4(v0[4],v0[5],v0[6],v0[7]));
        __stcg((float4*)(c1),   make_float4(v1[0],v1[1],v1[2],v1[3]));
        __stcg((float4*)(c1+4), make_float4(v1[4],v1[5],v1[6],v1[7]));
    }
}

__global__ void init_kernel(const float* __restrict__ hxs)
{
    if (blockIdx.x==0 && threadIdx.x==0){ g_arrive=0u; g_release=0u; }
    size_t i = (size_t)blockIdx.x*256 + threadIdx.x;
    ((float4*)g_h[0])[i] = ((const float4*)hxs)[i];
}

// ================= Persistent LSTM =================
// 128 blocks = 4 b-tiles(32 rows) x 32 h-tiles(16 h), 256 threads.
// Weights (128KB/CTA) L1-resident via __ldg (no fences -> no IVALL).
// h & xg staged cooperatively into smem (__ldcv / __ldcg). FFMA2 dot products.
// Barrier: atom.acq_rel arrive + ld.acquire poll. Streaming outputs via __stcg.
#define HS_STRIDE 516
__global__ __launch_bounds__(256)
void lstm_kernel(const float* __restrict__ Whh, const float* __restrict__ cxs,
                 float* __restrict__ dout)
{
    extern __shared__ __align__(16) float smem[];
    float* hsm = smem;                        // 32 rows x HS_STRIDE (66,048B)
    float* xsm = hsm + 32*HS_STRIDE;          // 32 x 4 x 16 (8KB)
    float* STb = xsm + 32*64;                 // 5 x 32 x 16 (10KB)
#define ST(a,r,q) STb[(((a)*32+(r))*16)+(q)]
    const int tid = threadIdx.x;
    const int b0 = (blockIdx.x & 3) * 32;
    const int hbase = (blockIdx.x >> 2) * 16;
    const int hloc = tid >> 4;        // 0..15
    const int bg = tid & 15;          // 0..15 -> 2 b rows
    const int h = hbase + hloc;
    const int rA = bg*2, rB = rA+1;
    const int bA = b0+rA, bB = b0+rB;

    const float* w0 = Whh + (size_t)(0*HHD + h)*HHD;
    const float* w1 = Whh + (size_t)(1*HHD + h)*HHD;
    const float* w2 = Whh + (size_t)(2*HHD + h)*HHD;
    const float* w3 = Whh + (size_t)(3*HHD + h)*HHD;
    const float* hrowA = hsm + rA*HS_STRIDE;
    const float* hrowB = hsm + rB*HS_STRIDE;

    float cA = cxs[(size_t)bA*HHD + h];
    float cB = cxs[(size_t)bB*HHD + h];

    float* outb = g_enc1;
    float* gp1 = dout + OFF_IG;  float* gp2 = dout + OFF_FG;
    float* gp3 = dout + OFF_GG;  float* gp4 = dout + OFF_OG;

    for (int t=0;t<TT;t++){
        const float* hin = g_h[t&1];
        float* hnx = g_h[(t+1)&1];

        // stage h tile (32 x 512) via ldcv (must see remote SM writes)
#pragma unroll
        for (int l=tid;l<4096;l+=256){
            int r = l>>7, c4 = (l&127)<<2;
            float4 v = __ldcv((const float4*)(hin + (size_t)(b0+r)*HHD + c4));
            *(float4*)&hsm[r*HS_STRIDE + c4] = v;
        }
        // stage xg tile (32 rows x 4 gates x 16 h) coalesced
#pragma unroll
        for (int l=tid;l<512;l+=256){
            int r = l>>4, rem = l&15, g = rem>>2, q4 = (rem&3)<<2;
            float4 v = __ldcg((const float4*)(g_xg + ((size_t)(b0+r)*TT + t)*G4 + (size_t)g*HHD + hbase + q4));
            *(float4*)&xsm[r*64 + g*16 + q4] = v;
        }
        __syncthreads();

        unsigned long long A0=0,A1=0,A2=0,A3=0,B0=0,B1=0,B2=0,B3=0;
#pragma unroll 4
        for (int k=0;k<HHD;k+=4){
            ulonglong2 wa = __ldg((const ulonglong2*)(w0+k));
            ulonglong2 wb = __ldg((const ulonglong2*)(w1+k));
            ulonglong2 wc = __ldg((const ulonglong2*)(w2+k));
            ulonglong2 wd = __ldg((const ulonglong2*)(w3+k));
            ulonglong2 hA = *(const ulonglong2*)(hrowA+k);
            ulonglong2 hB = *(const ulonglong2*)(hrowB+k);
            fma2(A0,hA.x,wa.x); fma2(A0,hA.y,wa.y);
            fma2(A1,hA.x,wb.x); fma2(A1,hA.y,wb.y);
            fma2(A2,hA.x,wc.x); fma2(A2,hA.y,wc.y);
            fma2(A3,hA.x,wd.x); fma2(A3,hA.y,wd.y);
            fma2(B0,hB.x,wa.x); fma2(B0,hB.y,wa.y);
            fma2(B1,hB.x,wb.x); fma2(B1,hB.y,wb.y);
            fma2(B2,hB.x,wc.x); fma2(B2,hB.y,wc.y);
            fma2(B3,hB.x,wd.x); fma2(B3,hB.y,wd.y);
        }
        float a0,a0h,a1,a1h,a2,a2h,a3,a3h,d0,d0h,d1,d1h,d2,d2h,d3,d3h;
        unpack2(A0,a0,a0h); unpack2(A1,a1,a1h); unpack2(A2,a2,a2h); unpack2(A3,a3,a3h);
        unpack2(B0,d0,d0h); unpack2(B1,d1,d1h); unpack2(B2,d2,d2h); unpack2(B3,d3,d3h);
        a0+=a0h; a1+=a1h; a2+=a2h; a3+=a3h;
        d0+=d0h; d1+=d1h; d2+=d2h; d3+=d3h;

        float iA = sigf(a0 + xsm[rA*64 + 0*16 + hloc]);
        float fA = sigf(a1 + xsm[rA*64 + 1*16 + hloc]);
        float gA = tanhf(a2 + xsm[rA*64 + 2*16 + hloc]);
        float oA = sigf(a3 + xsm[rA*64 + 3*16 + hloc]);
        float iB = sigf(d0 + xsm[rB*64 + 0*16 + hloc]);
        float fB = sigf(d1 + xsm[rB*64 + 1*16 + hloc]);
        float gB = tanhf(d2 + xsm[rB*64 + 2*16 + hloc]);
        float oB = sigf(d3 + xsm[rB*64 + 3*16 + hloc]);
        cA = fA*cA + iA*gA;  cB = fB*cB + iB*gB;
        float hAo = oA*tanhf(cA), hBo = oB*tanhf(cB);

        __syncthreads();   // done reading hsm/xsm this step
        ST(0,rA,hloc)=hAo; ST(0,rB,hloc)=hBo;
        ST(1,rA,hloc)=iA;  ST(1,rB,hloc)=iB;
        ST(2,rA,hloc)=fA;  ST(2,rB,hloc)=fB;
        ST(3,rA,hloc)=gA;  ST(3,rB,hloc)=gB;
        ST(4,rA,hloc)=oA;  ST(4,rB,hloc)=oB;
        __syncthreads();

        // h: 128 float4 slots; gates: 1024 float2 slots (gate sections of d_out
        // are only 8B-aligned: OFF_IG*4 == 8 mod 16). Streaming stores.
        for (int l=tid;l<1152;l+=256){
            if (l < 128){
                int r = l>>2, q4 = (l&3)<<2;
                float4 v = *(const float4*)&ST(0,r,q4);
                __stcg((float4*)(hnx + (size_t)(b0+r)*HHD + hbase + q4), v);
                __stcg((float4*)(outb + ((size_t)(b0+r)*TT + t)*HHD + hbase + q4), v);
            } else {
                int m = l - 128;
                int a = m >> 8;
                int r = (m >> 3) & 31;
                int q2 = (m & 7) << 1;
                float2 v = *(const float2*)&ST(a+1,r,q2);
                size_t base = ((size_t)(b0+r)*TT + t)*HHD + hbase + q2;
                float* gp = (a==0) ? gp1 : (a==1) ? gp2 : (a==2) ? gp3 : gp4;
                __stcg((float2*)(gp + base), v);
            }
        }

        if (t==TT-1){
            dout[OFF_HT + (size_t)bA*HHD + h] = hAo;
            dout[OFF_HT + (size_t)bB*HHD + h] = hBo;
            dout[OFF_CT + (size_t)bA*HHD + h] = cA;
            dout[OFF_CT + (size_t)bB*HHD + h] = cB;
        }

        __syncthreads();   // all stores (incl. hnx) issued before arrive
        if (tid==0){
            unsigned v;
            asm volatile("atom.acq_rel.gpu.global.add.u32 %0, [%1], %2;"
                         : "=r"(v) : "l"(&g_arrive), "r"(1u) : "memory");
            if (v == 127u){
                g_arrive = 0u;
                asm volatile("st.release.gpu.global.u32 [%0], %1;"
                             :: "l"(&g_release), "r"((unsigned)(t+1)) : "memory");
            } else {
                unsigned r;
                do {
                    asm volatile("ld.acquire.gpu.global.u32 %0, [%1];"
                                 : "=r"(r) : "l"(&g_release) : "memory");
                } while (r < (unsigned)(t+1));
            }
        }
        __syncthreads();
    }
#undef ST
}

__global__ __launch_bounds__(256)
void head_kernel(const float* __restrict__ Wa, const float* __restrict__ ba,
                 const float* __restrict__ Wc, const float* __restrict__ bc,
                 float* __restrict__ dout)
{
    __shared__ __align__(16) float xsr[16][516];
    const int tid = threadIdx.x;
    const size_t m0 = (size_t)blockIdx.x * 16;
    for (int l=tid;l<2048;l+=256){
        int r=l>>7, c4=(l&127)<<2;
        *(float4*)&xsr[r][c4] = *(const float4*)(g_enc1 + (m0+r)*HHD + c4);
    }
    __syncthreads();
    for (int o=tid;o<16*19;o+=256){
        int r=o/19, n=o-r*19;
        const float* wrow = (n<18) ? (Wa + (size_t)n*HHD) : Wc;
        float acc=0.f;
#pragma unroll 4
        for (int k=0;k<HHD;k+=4){
            float4 w = __ldg((const float4*)(wrow+k));
            float4 x = *(const float4*)&xsr[r][k];
            acc += x.x*w.x + x.y*w.y + x.z*w.z + x.w*w.w;
        }
        size_t m = m0 + r;
        if (n<18) dout[OFF_LOGITS + m*AA + n] = acc + ba[n];
        else      dout[OFF_VALUES + m] = acc + bc[0];
    }
}

__global__ __launch_bounds__(256)
void loss_partial()
{
    float s1=0.f, s2=0.f;
    const size_t n = (size_t)MM*HHD;
    for (size_t i=(size_t)blockIdx.x*256+threadIdx.x; i<n; i+=(size_t)LOSS_BLOCKS*256){
        float x = g_enc1[i];
        s1 += x*x;
        unsigned t = ((unsigned)(i>>9)) & 511u;
        if (t != 511u){ float d = g_enc1[i+512] - x; s2 += d*d; }
    }
    __shared__ double r1[256], r2[256];
    r1[threadIdx.x]=(double)s1; r2[threadIdx.x]=(double)s2;
    __syncthreads();
    for (int s=128;s>0;s>>=1){
        if (threadIdx.x<s){ r1[threadIdx.x]+=r1[threadIdx.x+s]; r2[threadIdx.x]+=r2[threadIdx.x+s]; }
        __syncthreads();
    }
    if (threadIdx.x==0){ g_part[0][blockIdx.x]=r1[0]; g_part[1][blockIdx.x]=r2[0]; }
}

__global__ void loss_final(float* __restrict__ dout)
{
    __shared__ double r1[256], r2[256];
    double s1=0.0, s2=0.0;
    for (int i=threadIdx.x;i<LOSS_BLOCKS;i+=256){ s1+=g_part[0][i]; s2+=g_part[1][i]; }
    r1[threadIdx.x]=s1; r2[threadIdx.x]=s2;
    __syncthreads();
    for (int s=128;s>0;s>>=1){
        if (threadIdx.x<s){ r1[threadIdx.x]+=r1[threadIdx.x+s]; r2[threadIdx.x]+=r2[threadIdx.x+s]; }
        __syncthreads();
    }
    if (threadIdx.x==0){
        dout[OFF_AR]  = (float)(r1[0] * (0.01 / ((double)MM * HHD)));
        dout[OFF_TAR] = (float)(r2[0] * (0.01 / ((double)BB * (TT-1) * HHD)));
    }
}

extern "C" void kernel_launch(void* const* d_in, const int* in_sizes, int n_in,
                              void* d_out, int out_size)
{
    const float* obs  = (const float*)d_in[0];
    const float* hxs  = (const float*)d_in[1];
    const float* cxs  = (const float*)d_in[2];
    const float* W1   = (const float*)d_in[3];
    const float* b1   = (const float*)d_in[4];
    const float* W2   = (const float*)d_in[5];
    const float* b2   = (const float*)d_in[6];
    const float* W_ih = (const float*)d_in[7];
    const float* W_hh = (const float*)d_in[8];
    const float* b_ih = (const float*)d_in[9];
    const float* b_hh = (const float*)d_in[10];
    const float* Wa   = (const float*)d_in[11];
    const float* ba   = (const float*)d_in[12];
    const float* Wc   = (const float*)d_in[13];
    const float* bc   = (const float*)d_in[14];
    float* dout = (float*)d_out;

    float* enc1; cudaGetSymbolAddress((void**)&enc1, g_enc1);
    float* enc2; cudaGetSymbolAddress((void**)&enc2, g_enc2);
    float* xg;   cudaGetSymbolAddress((void**)&xg,   g_xg);

    const int lstm_smem = (32*HS_STRIDE + 32*64 + 5*32*16) * (int)sizeof(float);
    cudaFuncSetAttribute(lstm_kernel, cudaFuncAttributeMaxDynamicSharedMemorySize, lstm_smem);

    init_kernel<<<64, 256>>>(hxs);   // first, so ncu skip-5 lands on gemm3
    // enc1 = silu(obs @ W1^T + b1)   [65536 x 512, K=128]
    gemm_nt<1><<<dim3(ENC/128, MM/128), 256>>>(obs, W1, b1, nullptr, enc1, 128, ENC);
    // enc2 = silu(enc1 @ W2^T + b2)  [65536 x 512, K=512]
    gemm_nt<1><<<dim3(ENC/128, MM/128), 256>>>(enc1, W2, b2, nullptr, enc2, ENC, ENC);
    // xg = enc2 @ W_ih^T + b_ih + b_hh   [65536 x 2048, K=512]
    gemm_nt<0><<<dim3(G4/128, MM/128), 256>>>(enc2, W_ih, b_ih, b_hh, xg, ENC, G4);

    lstm_kernel<<<128, 256, lstm_smem>>>(W_hh, cxs, dout);
    head_kernel<<<MM/16, 256>>>(Wa, ba, Wc, bc, dout);
    loss_partial<<<LOSS_BLOCKS, 256>>>();
    loss_final<<<1, 256>>>(dout);
}